// round 6
// baseline (speedup 1.0000x reference)
#include <cuda_runtime.h>
#include <math.h>

// Problem constants: B=2, T=8, N=65536, M=128, F=5, S=128
#define B_ 2
#define T_ 8
#define N_ 65536
#define M_ 128
#define F_ 5
#define S_ 128
#define GAMMA_ 1.1f

#define NTHREADS 256
#define WARPS_PER_CTA 8
#define NWARPSG (B_ * T_ * M_)          // 2048 rois = 2048 warps
#define STAGE_PTS 512                   // points per warp-stage (16/thread)
#define NSTAGES (N_ / STAGE_PTS)        // 128
#define TOTALPTS (B_ * T_ * N_)         // 1,048,576

// SoA scratch for xy (predicate scan reads these coalesced).
__device__ __align__(16) float g_x[TOTALPTS];
__device__ __align__(16) float g_y[TOTALPTS];

// Vectorized AoS->SoA transpose: 4 points (= 5 float4) per thread.
__global__ __launch_bounds__(NTHREADS)
void transpose_xy_kernel(const float4* __restrict__ pts4)
{
    const int i4 = blockIdx.x * NTHREADS + threadIdx.x;
    const float4 p0 = pts4[i4 * 5 + 0];
    const float4 p1 = pts4[i4 * 5 + 1];
    const float4 p2 = pts4[i4 * 5 + 2];
    const float4 p3 = pts4[i4 * 5 + 3];
    const float4 p4 = pts4[i4 * 5 + 4];
    ((float4*)g_x)[i4] = make_float4(p0.x, p1.y, p2.z, p3.w);
    ((float4*)g_y)[i4] = make_float4(p0.y, p1.z, p2.w, p4.x);
}

// ---- packed f32x2 helpers (per-lane exact .rn => bit-identical to scalar) ----
__device__ __forceinline__ unsigned long long pk2(float lo, float hi) {
    unsigned long long r;
    asm("mov.b64 %0, {%1, %2};" : "=l"(r) : "f"(lo), "f"(hi));
    return r;
}
__device__ __forceinline__ unsigned long long sub2(unsigned long long a,
                                                   unsigned long long b) {
    unsigned long long d;
    asm("sub.rn.f32x2 %0, %1, %2;" : "=l"(d) : "l"(a), "l"(b));
    return d;
}
__device__ __forceinline__ unsigned long long mul2(unsigned long long a,
                                                   unsigned long long b) {
    unsigned long long d;
    asm("mul.rn.f32x2 %0, %1, %2;" : "=l"(d) : "l"(a), "l"(b));
    return d;
}
__device__ __forceinline__ unsigned long long add2(unsigned long long a,
                                                   unsigned long long b) {
    unsigned long long d;
    asm("add.rn.f32x2 %0, %1, %2;" : "=l"(d) : "l"(a), "l"(b));
    return d;
}
__device__ __forceinline__ void unpk2(unsigned long long v, float& lo, float& hi) {
    asm("mov.b64 {%0, %1}, %2;" : "=f"(lo), "=f"(hi) : "l"(v));
}

struct StageBuf { float4 x[4]; float4 y[4]; };

__device__ __forceinline__ void load_stage(StageBuf& sb, const float4* __restrict__ X4,
                                           const float4* __restrict__ Y4,
                                           int s, int lane)
{
    const int b4 = s * (STAGE_PTS / 4);
    #pragma unroll
    for (int g = 0; g < 4; g++) {
        sb.x[g] = X4[b4 + g * 32 + lane];
        sb.y[g] = Y4[b4 + g * 32 + lane];
    }
}

// Build 16-bit mask; bit g*4+k corresponds to point s*512 + g*128 + lane*4 + k.
__device__ __forceinline__ unsigned stage_mask(const StageBuf& sb,
                                               unsigned long long cx2,
                                               unsigned long long cy2, float thr)
{
    unsigned mask = 0;
    #pragma unroll
    for (int g = 0; g < 4; g++) {
        const unsigned long long x01 = pk2(sb.x[g].x, sb.x[g].y);
        const unsigned long long x23 = pk2(sb.x[g].z, sb.x[g].w);
        const unsigned long long y01 = pk2(sb.y[g].x, sb.y[g].y);
        const unsigned long long y23 = pk2(sb.y[g].z, sb.y[g].w);
        const unsigned long long dx01 = sub2(x01, cx2);
        const unsigned long long dx23 = sub2(x23, cx2);
        const unsigned long long dy01 = sub2(y01, cy2);
        const unsigned long long dy23 = sub2(y23, cy2);
        const unsigned long long d01 = add2(mul2(dx01, dx01), mul2(dy01, dy01));
        const unsigned long long d23 = add2(mul2(dx23, dx23), mul2(dy23, dy23));
        float d0, d1, d2, d3;
        unpk2(d01, d0, d1);
        unpk2(d23, d2, d3);
        mask |= (d0 <= thr ? 1u : 0u) << (g * 4 + 0);
        mask |= (d1 <= thr ? 1u : 0u) << (g * 4 + 1);
        mask |= (d2 <= thr ? 1u : 0u) << (g * 4 + 2);
        mask |= (d3 <= thr ? 1u : 0u) << (g * 4 + 3);
    }
    return mask;
}

// Warp-only ordered write of a matching stage. Returns stage total (uniform).
__device__ __forceinline__ int emit_stage(unsigned mask, int total, int s, int lane,
                                          const float* __restrict__ P,
                                          float* __restrict__ O)
{
    // Byte-packed per-group counts; per-group warp sums <= 128, no carry.
    unsigned cp = 0;
    #pragma unroll
    for (int g = 0; g < 4; g++)
        cp |= (unsigned)__popc((mask >> (4 * g)) & 0xFu) << (8 * g);

    unsigned incl = cp;
    #pragma unroll
    for (int d = 1; d < 32; d <<= 1) {
        const unsigned v = __shfl_up_sync(0xFFFFFFFFu, incl, d);
        if (lane >= d) incl += v;
    }
    const unsigned wtot = __shfl_sync(0xFFFFFFFFu, incl, 31);
    const unsigned excl = incl - cp;

    if (mask) {
        int fp = 0;
        #pragma unroll
        for (int g = 0; g < 4; g++) {
            int r = total + fp + (int)((excl >> (8 * g)) & 0xFFu);
            unsigned mj = (mask >> (4 * g)) & 0xFu;
            while (mj) {
                const int k = __ffs(mj) - 1;
                mj &= mj - 1;
                if (r < S_) {
                    const int pt = s * STAGE_PTS + g * 128 + lane * 4 + k;
                    const float* src = P + (size_t)pt * F_;
                    float* dst = O + r * F_;
                    #pragma unroll
                    for (int f = 0; f < F_; f++) dst[f] = src[f];
                }
                r++;
            }
            fp += (int)((wtot >> (8 * g)) & 0xFFu);
        }
    }
    const unsigned a = (wtot & 0x00FF00FFu) + ((wtot >> 8) & 0x00FF00FFu);
    return (int)((a & 0xFFFFu) + (a >> 16));
}

// One WARP per (b, t, m). No smem, no CTA barriers.
__global__ __launch_bounds__(NTHREADS, 2)
void voxel_pool_kernel(const float* __restrict__ pts,
                       const float* __restrict__ rois,
                       const int* __restrict__ vl,
                       float* __restrict__ out)
{
    const int gw = blockIdx.x * WARPS_PER_CTA + (threadIdx.x >> 5);
    const int lane = threadIdx.x & 31;
    const int m = gw & (M_ - 1);
    const int t = (gw >> 7) & (T_ - 1);
    const int b = gw >> 10;

    int use_t = t;
    if (t != 0 && vl[(b * T_ + t) * M_ + m] == 0) use_t = 0;

    const int slab = b * T_ + use_t;
    const float*  P  = pts + (size_t)slab * N_ * F_;
    const float4* X4 = (const float4*)(g_x + (size_t)slab * N_);
    const float4* Y4 = (const float4*)(g_y + (size_t)slab * N_);
    float* O = out + ((size_t)(b * M_ + m) * (T_ * S_) + (size_t)t * S_) * F_;

    // Prime the 3-deep pipeline before roi setup (loads don't need the roi).
    StageBuf A, Bb, C;
    load_stage(A,  X4, Y4, 0, lane);
    load_stage(Bb, X4, Y4, 1, lane);
    load_stage(C,  X4, Y4, 2, lane);

    // Roi setup, redundantly per lane (uniform, overlaps the loads above).
    const float* roi = rois + ((size_t)slab * M_ + m) * 7;
    const float cx = roi[0];
    const float cy = roi[1];
    const float hl = __fmul_rn(roi[3], 0.5f);
    const float hw = __fmul_rn(roi[4], 0.5f);
    const float rr = __fmul_rn(
        sqrtf(__fadd_rn(__fmul_rn(hl, hl), __fmul_rn(hw, hw))), GAMMA_);
    // Largest float x with sqrtf(x) <= rr: (d2 <= thr) is bit-identical to
    // (sqrtf(d2) <= rr); removes the per-point sqrt.
    float thr = __fmul_rn(rr, rr);
    while (sqrtf(thr) > rr) thr = __int_as_float(__float_as_int(thr) - 1);
    for (;;) {
        float nxt = __int_as_float(__float_as_int(thr) + 1);
        if (sqrtf(nxt) <= rr) thr = nxt; else break;
    }
    const unsigned long long cx2 = pk2(cx, cx);
    const unsigned long long cy2 = pk2(cy, cy);

    int total = 0;
    #pragma unroll 1
    for (int s = 0; s < NSTAGES; s += 3) {
        // stage s (buffer A)
        {
            const unsigned mask = stage_mask(A, cx2, cy2, thr);
            if (__ballot_sync(0xFFFFFFFFu, mask != 0))
                total = total + emit_stage(mask, total, s, lane, P, O);
            if (total >= S_) break;
            const int ns = s + 3;
            load_stage(A, X4, Y4, ns < NSTAGES ? ns : 0, lane);
        }
        // stage s+1 (buffer Bb)
        {
            const unsigned mask = stage_mask(Bb, cx2, cy2, thr);
            if (__ballot_sync(0xFFFFFFFFu, mask != 0))
                total = total + emit_stage(mask, total, s + 1, lane, P, O);
            if (total >= S_) break;
            const int ns = s + 4;
            load_stage(Bb, X4, Y4, ns < NSTAGES ? ns : 0, lane);
        }
        // stage s+2 (buffer C) — NSTAGES % 3 == 2, so the final iteration
        // (s == 126) has no valid third sub-stage; buffer C then holds
        // clamped stage-0 data and MUST NOT be emitted.
        if (s + 2 < NSTAGES) {
            const unsigned mask = stage_mask(C, cx2, cy2, thr);
            if (__ballot_sync(0xFFFFFFFFu, mask != 0))
                total = total + emit_stage(mask, total, s + 2, lane, P, O);
            if (total >= S_) break;
            const int ns = s + 5;
            load_stage(C, X4, Y4, ns < NSTAGES ? ns : 0, lane);
        }
    }

    // Zero-fill rows [written, S).
    const int written = (total < S_) ? total : S_;
    const int zfl = (S_ - written) * F_;
    for (int i = lane; i < zfl; i += 32) {
        O[written * F_ + i] = 0.0f;
    }
}

extern "C" void kernel_launch(void* const* d_in, const int* in_sizes, int n_in,
                              void* d_out, int out_size)
{
    const float* pts  = (const float*)d_in[0];  // [B,T,N,F] f32
    const float* rois = (const float*)d_in[1];  // [B,T,M,7] f32
    const int*   vl   = (const int*)d_in[2];    // [B,T,M]   i32
    float* out = (float*)d_out;                 // [B,M,T*S,F] f32

    (void)in_sizes; (void)n_in; (void)out_size;
    transpose_xy_kernel<<<TOTALPTS / 4 / NTHREADS, NTHREADS>>>((const float4*)pts);
    voxel_pool_kernel<<<NWARPSG / WARPS_PER_CTA, NTHREADS>>>(pts, rois, vl, out);
}

// round 7
// speedup vs baseline: 1.2714x; 1.2714x over previous
#include <cuda_runtime.h>
#include <math.h>

// Problem constants: B=2, T=8, N=65536, M=128, F=5, S=128
#define B_ 2
#define T_ 8
#define N_ 65536
#define M_ 128
#define F_ 5
#define S_ 128
#define GAMMA_ 1.1f

#define NTHREADS 256
#define WARPS_PER_CTA 8
#define NWARPSG (B_ * T_ * M_)          // 2048 rois
#define STAGE_PTS 512                   // points per warp-stage (16/lane)
#define CAP_STAGES 48                   // phase-1 cap (divisible by 3)
#define CAP_PTS (CAP_STAGES * STAGE_PTS)        // 24576
#define TOTALPTS (B_ * T_ * N_)         // 1,048,576

// Phase 2 config: 512-thread CTA, 16 pts/thread -> 8192-pt chunks.
#define P2T 512
#define P2W 16
#define P2CHUNK (P2T * 16)              // 8192
#define P2NCH ((N_ - CAP_PTS) / P2CHUNK)        // 5
#define P2GRID 256

// SoA scratch for xy + phase-1 -> phase-2 handoff state.
__device__ __align__(16) float g_x[TOTALPTS];
__device__ __align__(16) float g_y[TOTALPTS];
__device__ int g_nq;
__device__ int g_queue[NWARPSG];
__device__ int g_total[NWARPSG];

// Vectorized AoS->SoA transpose: 4 points (= 5 float4) per thread.
// Also resets the phase-2 queue counter (stream-ordered before phase 1).
__global__ __launch_bounds__(NTHREADS)
void transpose_xy_kernel(const float4* __restrict__ pts4)
{
    if (blockIdx.x == 0 && threadIdx.x == 0) g_nq = 0;
    const int i4 = blockIdx.x * NTHREADS + threadIdx.x;
    const float4 p0 = pts4[i4 * 5 + 0];
    const float4 p1 = pts4[i4 * 5 + 1];
    const float4 p2 = pts4[i4 * 5 + 2];
    const float4 p3 = pts4[i4 * 5 + 3];
    const float4 p4 = pts4[i4 * 5 + 4];
    ((float4*)g_x)[i4] = make_float4(p0.x, p1.y, p2.z, p3.w);
    ((float4*)g_y)[i4] = make_float4(p0.y, p1.z, p2.w, p4.x);
}

// ---- packed f32x2 helpers (per-lane exact .rn => bit-identical to scalar) ----
__device__ __forceinline__ unsigned long long pk2(float lo, float hi) {
    unsigned long long r;
    asm("mov.b64 %0, {%1, %2};" : "=l"(r) : "f"(lo), "f"(hi));
    return r;
}
__device__ __forceinline__ unsigned long long sub2(unsigned long long a,
                                                   unsigned long long b) {
    unsigned long long d;
    asm("sub.rn.f32x2 %0, %1, %2;" : "=l"(d) : "l"(a), "l"(b));
    return d;
}
__device__ __forceinline__ unsigned long long mul2(unsigned long long a,
                                                   unsigned long long b) {
    unsigned long long d;
    asm("mul.rn.f32x2 %0, %1, %2;" : "=l"(d) : "l"(a), "l"(b));
    return d;
}
__device__ __forceinline__ unsigned long long add2(unsigned long long a,
                                                   unsigned long long b) {
    unsigned long long d;
    asm("add.rn.f32x2 %0, %1, %2;" : "=l"(d) : "l"(a), "l"(b));
    return d;
}
__device__ __forceinline__ void unpk2(unsigned long long v, float& lo, float& hi) {
    asm("mov.b64 {%0, %1}, %2;" : "=f"(lo), "=f"(hi) : "l"(v));
}

__device__ __forceinline__ unsigned long long spread4(unsigned v)
{
    return (unsigned long long)(v & 0xFFu)
         | ((unsigned long long)(v & 0xFF00u)     << 8)
         | ((unsigned long long)(v & 0xFF0000u)   << 16)
         | ((unsigned long long)(v & 0xFF000000u) << 24);
}

// thr = largest float x with sqrtf(x) <= r  => (d2 <= thr) bit-identical to
// (sqrtf(d2) <= r); removes the per-point sqrt.
__device__ __forceinline__ float roi_setup(const float* __restrict__ roi,
                                           float& cx, float& cy)
{
    cx = roi[0];
    cy = roi[1];
    const float hl = __fmul_rn(roi[3], 0.5f);
    const float hw = __fmul_rn(roi[4], 0.5f);
    const float rr = __fmul_rn(
        sqrtf(__fadd_rn(__fmul_rn(hl, hl), __fmul_rn(hw, hw))), GAMMA_);
    float thr = __fmul_rn(rr, rr);
    while (sqrtf(thr) > rr) thr = __int_as_float(__float_as_int(thr) - 1);
    for (;;) {
        float nxt = __int_as_float(__float_as_int(thr) + 1);
        if (sqrtf(nxt) <= rr) thr = nxt; else break;
    }
    return thr;
}

struct StageBuf { float4 x[4]; float4 y[4]; };

__device__ __forceinline__ void load_stage(StageBuf& sb, const float4* __restrict__ X4,
                                           const float4* __restrict__ Y4,
                                           int s, int lane)
{
    const int b4 = s * (STAGE_PTS / 4);
    #pragma unroll
    for (int g = 0; g < 4; g++) {
        sb.x[g] = X4[b4 + g * 32 + lane];
        sb.y[g] = Y4[b4 + g * 32 + lane];
    }
}

__device__ __forceinline__ unsigned stage_mask(const StageBuf& sb,
                                               unsigned long long cx2,
                                               unsigned long long cy2, float thr)
{
    unsigned mask = 0;
    #pragma unroll
    for (int g = 0; g < 4; g++) {
        const unsigned long long x01 = pk2(sb.x[g].x, sb.x[g].y);
        const unsigned long long x23 = pk2(sb.x[g].z, sb.x[g].w);
        const unsigned long long y01 = pk2(sb.y[g].x, sb.y[g].y);
        const unsigned long long y23 = pk2(sb.y[g].z, sb.y[g].w);
        const unsigned long long dx01 = sub2(x01, cx2);
        const unsigned long long dx23 = sub2(x23, cx2);
        const unsigned long long dy01 = sub2(y01, cy2);
        const unsigned long long dy23 = sub2(y23, cy2);
        const unsigned long long d01 = add2(mul2(dx01, dx01), mul2(dy01, dy01));
        const unsigned long long d23 = add2(mul2(dx23, dx23), mul2(dy23, dy23));
        float d0, d1, d2, d3;
        unpk2(d01, d0, d1);
        unpk2(d23, d2, d3);
        mask |= (d0 <= thr ? 1u : 0u) << (g * 4 + 0);
        mask |= (d1 <= thr ? 1u : 0u) << (g * 4 + 1);
        mask |= (d2 <= thr ? 1u : 0u) << (g * 4 + 2);
        mask |= (d3 <= thr ? 1u : 0u) << (g * 4 + 3);
    }
    return mask;
}

// Warp-only ordered write of a matching stage. Returns stage total (uniform).
__device__ __forceinline__ int emit_stage(unsigned mask, int total, int s, int lane,
                                          const float* __restrict__ P,
                                          float* __restrict__ O)
{
    unsigned cp = 0;
    #pragma unroll
    for (int g = 0; g < 4; g++)
        cp |= (unsigned)__popc((mask >> (4 * g)) & 0xFu) << (8 * g);

    unsigned incl = cp;
    #pragma unroll
    for (int d = 1; d < 32; d <<= 1) {
        const unsigned v = __shfl_up_sync(0xFFFFFFFFu, incl, d);
        if (lane >= d) incl += v;
    }
    const unsigned wtot = __shfl_sync(0xFFFFFFFFu, incl, 31);
    const unsigned excl = incl - cp;

    if (mask) {
        int fp = 0;
        #pragma unroll
        for (int g = 0; g < 4; g++) {
            int r = total + fp + (int)((excl >> (8 * g)) & 0xFFu);
            unsigned mj = (mask >> (4 * g)) & 0xFu;
            while (mj) {
                const int k = __ffs(mj) - 1;
                mj &= mj - 1;
                if (r < S_) {
                    const int pt = s * STAGE_PTS + g * 128 + lane * 4 + k;
                    const float* src = P + (size_t)pt * F_;
                    float* dst = O + r * F_;
                    #pragma unroll
                    for (int f = 0; f < F_; f++) dst[f] = src[f];
                }
                r++;
            }
            fp += (int)((wtot >> (8 * g)) & 0xFFu);
        }
    }
    const unsigned a = (wtot & 0x00FF00FFu) + ((wtot >> 8) & 0x00FF00FFu);
    return (int)((a & 0xFFFFu) + (a >> 16));
}

// Phase 1: one WARP per roi, capped at CAP_STAGES. Unfinished rois enqueue.
__global__ __launch_bounds__(NTHREADS, 2)
void voxel_phase1(const float* __restrict__ pts,
                  const float* __restrict__ rois,
                  const int* __restrict__ vl,
                  float* __restrict__ out)
{
    const int gw = blockIdx.x * WARPS_PER_CTA + (threadIdx.x >> 5);
    const int lane = threadIdx.x & 31;
    const int m = gw & (M_ - 1);
    const int t = (gw >> 7) & (T_ - 1);
    const int b = gw >> 10;

    int use_t = t;
    if (t != 0 && vl[(b * T_ + t) * M_ + m] == 0) use_t = 0;

    const int slab = b * T_ + use_t;
    const float*  P  = pts + (size_t)slab * N_ * F_;
    const float4* X4 = (const float4*)(g_x + (size_t)slab * N_);
    const float4* Y4 = (const float4*)(g_y + (size_t)slab * N_);
    float* O = out + ((size_t)(b * M_ + m) * (T_ * S_) + (size_t)t * S_) * F_;

    StageBuf A, Bb, C;
    load_stage(A,  X4, Y4, 0, lane);
    load_stage(Bb, X4, Y4, 1, lane);
    load_stage(C,  X4, Y4, 2, lane);

    float cx, cy;
    const float thr = roi_setup(rois + ((size_t)slab * M_ + m) * 7, cx, cy);
    const unsigned long long cx2 = pk2(cx, cx);
    const unsigned long long cy2 = pk2(cy, cy);

    int total = 0;
    #pragma unroll 1
    for (int s = 0; s < CAP_STAGES; s += 3) {   // CAP_STAGES % 3 == 0
        {
            const unsigned mask = stage_mask(A, cx2, cy2, thr);
            if (__ballot_sync(0xFFFFFFFFu, mask != 0))
                total = total + emit_stage(mask, total, s, lane, P, O);
            if (total >= S_) break;
            const int ns = s + 3;
            load_stage(A, X4, Y4, ns < CAP_STAGES ? ns : 0, lane);
        }
        {
            const unsigned mask = stage_mask(Bb, cx2, cy2, thr);
            if (__ballot_sync(0xFFFFFFFFu, mask != 0))
                total = total + emit_stage(mask, total, s + 1, lane, P, O);
            if (total >= S_) break;
            const int ns = s + 4;
            load_stage(Bb, X4, Y4, ns < CAP_STAGES ? ns : 0, lane);
        }
        {
            const unsigned mask = stage_mask(C, cx2, cy2, thr);
            if (__ballot_sync(0xFFFFFFFFu, mask != 0))
                total = total + emit_stage(mask, total, s + 2, lane, P, O);
            if (total >= S_) break;
            const int ns = s + 5;
            load_stage(C, X4, Y4, ns < CAP_STAGES ? ns : 0, lane);
        }
    }

    if (total < S_) {
        // Unfinished: hand off to phase 2 (which also does the zero-fill).
        if (lane == 0) {
            g_total[gw] = total;
            const int qi = atomicAdd(&g_nq, 1);
            g_queue[qi] = gw;
        }
    }
    // total >= S_: all 128 rows written, nothing left to do.
}

// Phase 2: one 512-thread CTA per unfinished roi, scanning [CAP_PTS, N).
__global__ __launch_bounds__(P2T)
void voxel_phase2(const float* __restrict__ pts,
                  const float* __restrict__ rois,
                  const int* __restrict__ vl,
                  float* __restrict__ out)
{
    __shared__ unsigned long long s_cnt[2][P2W];
    const int tid  = threadIdx.x;
    const int lane = tid & 31;
    const int wid  = tid >> 5;
    const int nq = g_nq;

    for (int qi = blockIdx.x; qi < nq; qi += gridDim.x) {
        const int gw = g_queue[qi];
        const int m = gw & (M_ - 1);
        const int t = (gw >> 7) & (T_ - 1);
        const int b = gw >> 10;

        int use_t = t;
        if (t != 0 && vl[(b * T_ + t) * M_ + m] == 0) use_t = 0;

        const int slab = b * T_ + use_t;
        const float*  P  = pts + (size_t)slab * N_ * F_;
        const float4* X4 = (const float4*)(g_x + (size_t)slab * N_);
        const float4* Y4 = (const float4*)(g_y + (size_t)slab * N_);
        float* O = out + ((size_t)(b * M_ + m) * (T_ * S_) + (size_t)t * S_) * F_;

        float cx, cy;
        const float thr = roi_setup(rois + ((size_t)slab * M_ + m) * 7, cx, cy);

        int total = g_total[gw];

        #pragma unroll 1
        for (int c = 0; c < P2NCH; c++) {
            const int base = CAP_PTS + c * P2CHUNK;
            const int b4 = base / 4;

            // point = base + g*2048 + tid*4 + k  (coalesced per g)
            unsigned mask = 0;
            #pragma unroll
            for (int g = 0; g < 4; g++) {
                const float4 xv = X4[b4 + g * P2T + tid];
                const float4 yv = Y4[b4 + g * P2T + tid];
                const float* xs = (const float*)&xv;
                const float* ys = (const float*)&yv;
                #pragma unroll
                for (int k = 0; k < 4; k++) {
                    const float dx = __fsub_rn(xs[k], cx);
                    const float dy = __fsub_rn(ys[k], cy);
                    const float d2 = __fadd_rn(__fmul_rn(dx, dx),
                                               __fmul_rn(dy, dy));
                    mask |= (d2 <= thr ? 1u : 0u) << (g * 4 + k);
                }
            }

            unsigned cp = 0;
            #pragma unroll
            for (int g = 0; g < 4; g++)
                cp |= (unsigned)__popc((mask >> (4 * g)) & 0xFu) << (8 * g);

            unsigned incl = cp;
            #pragma unroll
            for (int d = 1; d < 32; d <<= 1) {
                const unsigned v = __shfl_up_sync(0xFFFFFFFFu, incl, d);
                if (lane >= d) incl += v;
            }
            const unsigned wtot = __shfl_sync(0xFFFFFFFFu, incl, 31);
            const unsigned excl = incl - cp;

            if (lane == 0) s_cnt[c & 1][wid] = spread4(wtot);
            __syncthreads();

            unsigned long long tot64 = 0, bef64 = 0;
            #pragma unroll
            for (int w = 0; w < P2W; w++) {
                const unsigned long long v = s_cnt[c & 1][w];
                tot64 += v;
                if (w < wid) bef64 += v;
            }
            const unsigned a = (unsigned)tot64 + (unsigned)(tot64 >> 32);
            const int chunkTotal = (int)((a & 0xFFFFu) + (a >> 16));

            if (mask) {
                int fp = 0;
                #pragma unroll
                for (int g = 0; g < 4; g++) {
                    const int tj = (int)((tot64 >> (16 * g)) & 0xFFFFu);
                    const int bj = (int)((bef64 >> (16 * g)) & 0xFFFFu);
                    int r = total + fp + bj + (int)((excl >> (8 * g)) & 0xFFu);
                    unsigned mj = (mask >> (4 * g)) & 0xFu;
                    while (mj) {
                        const int k = __ffs(mj) - 1;
                        mj &= mj - 1;
                        if (r < S_) {
                            const int pt = base + g * (P2T * 4) + tid * 4 + k;
                            const float* src = P + (size_t)pt * F_;
                            float* dst = O + r * F_;
                            #pragma unroll
                            for (int f = 0; f < F_; f++) dst[f] = src[f];
                        }
                        r++;
                    }
                    fp += tj;
                }
            }

            total += chunkTotal;
            if (total >= S_) break;   // uniform
        }

        // Zero-fill rows [written, S).
        const int written = (total < S_) ? total : S_;
        const int zfl = (S_ - written) * F_;
        for (int i = tid; i < zfl; i += P2T) {
            O[written * F_ + i] = 0.0f;
        }
        __syncthreads();   // protect s_cnt before next queue entry
    }
}

extern "C" void kernel_launch(void* const* d_in, const int* in_sizes, int n_in,
                              void* d_out, int out_size)
{
    const float* pts  = (const float*)d_in[0];  // [B,T,N,F] f32
    const float* rois = (const float*)d_in[1];  // [B,T,M,7] f32
    const int*   vl   = (const int*)d_in[2];    // [B,T,M]   i32
    float* out = (float*)d_out;                 // [B,M,T*S,F] f32

    (void)in_sizes; (void)n_in; (void)out_size;
    transpose_xy_kernel<<<TOTALPTS / 4 / NTHREADS, NTHREADS>>>((const float4*)pts);
    voxel_phase1<<<NWARPSG / WARPS_PER_CTA, NTHREADS>>>(pts, rois, vl, out);
    voxel_phase2<<<P2GRID, P2T>>>(pts, rois, vl, out);
}

// round 8
// speedup vs baseline: 1.3165x; 1.0355x over previous
#include <cuda_runtime.h>
#include <math.h>

// Problem constants: B=2, T=8, N=65536, M=128, F=5, S=128
#define B_ 2
#define T_ 8
#define N_ 65536
#define M_ 128
#define F_ 5
#define S_ 128
#define GAMMA_ 1.1f

#define NTHREADS 256
#define WARPS_PER_CTA 8
#define NWARPSG (B_ * T_ * M_)          // 2048 rois
#define STAGE_PTS 512                   // points per warp-stage (16/lane)
#define CAP_STAGES 16                   // phase-1 cap (divisible by 2)
#define CAP_PTS (CAP_STAGES * STAGE_PTS)        // 8192
#define TOTALPTS (B_ * T_ * N_)         // 1,048,576

// Phase 2: 512-thread CTA, 16 pts/thread -> 8192-pt chunks; (N-CAP)/8192 = 7.
#define P2T 512
#define P2W 16
#define P2CHUNK (P2T * 16)              // 8192
#define P2NCH ((N_ - CAP_PTS) / P2CHUNK)        // 7
#define P2GRID 256

// SoA scratch for xy + phase-1 -> phase-2 handoff state.
__device__ __align__(16) float g_x[TOTALPTS];
__device__ __align__(16) float g_y[TOTALPTS];
__device__ int g_nq;
__device__ int g_queue[NWARPSG];
__device__ int g_total[NWARPSG];

// AoS->SoA transpose: 8 points (= 10 float4) per thread. Also resets the
// phase-2 queue counter (stream-ordered before phase 1).
__global__ __launch_bounds__(NTHREADS)
void transpose_xy_kernel(const float4* __restrict__ pts4)
{
    if (blockIdx.x == 0 && threadIdx.x == 0) g_nq = 0;
    const int i8 = blockIdx.x * NTHREADS + threadIdx.x;
    float4 p[10];
    #pragma unroll
    for (int i = 0; i < 10; i++) p[i] = pts4[i8 * 10 + i];
    // flat floats f0..f39: x_j = f[5j], y_j = f[5j+1], j = 0..7
    ((float4*)g_x)[i8 * 2 + 0] = make_float4(p[0].x, p[1].y, p[2].z, p[3].w);
    ((float4*)g_x)[i8 * 2 + 1] = make_float4(p[5].x, p[6].y, p[7].z, p[8].w);
    ((float4*)g_y)[i8 * 2 + 0] = make_float4(p[0].y, p[1].z, p[2].w, p[4].x);
    ((float4*)g_y)[i8 * 2 + 1] = make_float4(p[5].y, p[6].z, p[7].w, p[9].x);
}

// ---- packed f32x2 helpers (per-lane exact .rn => bit-identical to scalar) ----
__device__ __forceinline__ unsigned long long pk2(float lo, float hi) {
    unsigned long long r;
    asm("mov.b64 %0, {%1, %2};" : "=l"(r) : "f"(lo), "f"(hi));
    return r;
}
__device__ __forceinline__ unsigned long long sub2(unsigned long long a,
                                                   unsigned long long b) {
    unsigned long long d;
    asm("sub.rn.f32x2 %0, %1, %2;" : "=l"(d) : "l"(a), "l"(b));
    return d;
}
__device__ __forceinline__ unsigned long long mul2(unsigned long long a,
                                                   unsigned long long b) {
    unsigned long long d;
    asm("mul.rn.f32x2 %0, %1, %2;" : "=l"(d) : "l"(a), "l"(b));
    return d;
}
__device__ __forceinline__ unsigned long long add2(unsigned long long a,
                                                   unsigned long long b) {
    unsigned long long d;
    asm("add.rn.f32x2 %0, %1, %2;" : "=l"(d) : "l"(a), "l"(b));
    return d;
}
__device__ __forceinline__ void unpk2(unsigned long long v, float& lo, float& hi) {
    asm("mov.b64 {%0, %1}, %2;" : "=f"(lo), "=f"(hi) : "l"(v));
}

__device__ __forceinline__ unsigned long long spread4(unsigned v)
{
    return (unsigned long long)(v & 0xFFu)
         | ((unsigned long long)(v & 0xFF00u)     << 8)
         | ((unsigned long long)(v & 0xFF0000u)   << 16)
         | ((unsigned long long)(v & 0xFF000000u) << 24);
}

// thr = largest float x with sqrtf(x) <= r  => (d2 <= thr) bit-identical to
// (sqrtf(d2) <= r); removes the per-point sqrt.
__device__ __forceinline__ float roi_setup(const float* __restrict__ roi,
                                           float& cx, float& cy)
{
    cx = roi[0];
    cy = roi[1];
    const float hl = __fmul_rn(roi[3], 0.5f);
    const float hw = __fmul_rn(roi[4], 0.5f);
    const float rr = __fmul_rn(
        sqrtf(__fadd_rn(__fmul_rn(hl, hl), __fmul_rn(hw, hw))), GAMMA_);
    float thr = __fmul_rn(rr, rr);
    while (sqrtf(thr) > rr) thr = __int_as_float(__float_as_int(thr) - 1);
    for (;;) {
        float nxt = __int_as_float(__float_as_int(thr) + 1);
        if (sqrtf(nxt) <= rr) thr = nxt; else break;
    }
    return thr;
}

struct StageBuf { float4 x[4]; float4 y[4]; };

__device__ __forceinline__ void load_stage(StageBuf& sb, const float4* __restrict__ X4,
                                           const float4* __restrict__ Y4,
                                           int s, int lane)
{
    const int b4 = s * (STAGE_PTS / 4);
    #pragma unroll
    for (int g = 0; g < 4; g++) {
        sb.x[g] = X4[b4 + g * 32 + lane];
        sb.y[g] = Y4[b4 + g * 32 + lane];
    }
}

__device__ __forceinline__ unsigned stage_mask(const StageBuf& sb,
                                               unsigned long long cx2,
                                               unsigned long long cy2, float thr)
{
    unsigned mask = 0;
    #pragma unroll
    for (int g = 0; g < 4; g++) {
        const unsigned long long x01 = pk2(sb.x[g].x, sb.x[g].y);
        const unsigned long long x23 = pk2(sb.x[g].z, sb.x[g].w);
        const unsigned long long y01 = pk2(sb.y[g].x, sb.y[g].y);
        const unsigned long long y23 = pk2(sb.y[g].z, sb.y[g].w);
        const unsigned long long dx01 = sub2(x01, cx2);
        const unsigned long long dx23 = sub2(x23, cx2);
        const unsigned long long dy01 = sub2(y01, cy2);
        const unsigned long long dy23 = sub2(y23, cy2);
        const unsigned long long d01 = add2(mul2(dx01, dx01), mul2(dy01, dy01));
        const unsigned long long d23 = add2(mul2(dx23, dx23), mul2(dy23, dy23));
        float d0, d1, d2, d3;
        unpk2(d01, d0, d1);
        unpk2(d23, d2, d3);
        mask |= (d0 <= thr ? 1u : 0u) << (g * 4 + 0);
        mask |= (d1 <= thr ? 1u : 0u) << (g * 4 + 1);
        mask |= (d2 <= thr ? 1u : 0u) << (g * 4 + 2);
        mask |= (d3 <= thr ? 1u : 0u) << (g * 4 + 3);
    }
    return mask;
}

// Warp-only ordered write of a matching stage. Returns stage total (uniform).
__device__ __forceinline__ int emit_stage(unsigned mask, int total, int s, int lane,
                                          const float* __restrict__ P,
                                          float* __restrict__ O)
{
    unsigned cp = 0;
    #pragma unroll
    for (int g = 0; g < 4; g++)
        cp |= (unsigned)__popc((mask >> (4 * g)) & 0xFu) << (8 * g);

    unsigned incl = cp;
    #pragma unroll
    for (int d = 1; d < 32; d <<= 1) {
        const unsigned v = __shfl_up_sync(0xFFFFFFFFu, incl, d);
        if (lane >= d) incl += v;
    }
    const unsigned wtot = __shfl_sync(0xFFFFFFFFu, incl, 31);
    const unsigned excl = incl - cp;

    if (mask) {
        int fp = 0;
        #pragma unroll
        for (int g = 0; g < 4; g++) {
            int r = total + fp + (int)((excl >> (8 * g)) & 0xFFu);
            unsigned mj = (mask >> (4 * g)) & 0xFu;
            while (mj) {
                const int k = __ffs(mj) - 1;
                mj &= mj - 1;
                if (r < S_) {
                    const int pt = s * STAGE_PTS + g * 128 + lane * 4 + k;
                    const float* src = P + (size_t)pt * F_;
                    float* dst = O + r * F_;
                    #pragma unroll
                    for (int f = 0; f < F_; f++) dst[f] = src[f];
                }
                r++;
            }
            fp += (int)((wtot >> (8 * g)) & 0xFFu);
        }
    }
    const unsigned a = (wtot & 0x00FF00FFu) + ((wtot >> 8) & 0x00FF00FFu);
    return (int)((a & 0xFFFFu) + (a >> 16));
}

// Phase 1: one WARP per roi, capped at CAP_STAGES (8192 pts). Depth-2
// pipeline; CAP_STAGES % 2 == 0, so every emitted stage index is valid.
__global__ __launch_bounds__(NTHREADS, 2)
void voxel_phase1(const float* __restrict__ pts,
                  const float* __restrict__ rois,
                  const int* __restrict__ vl,
                  float* __restrict__ out)
{
    const int gw = blockIdx.x * WARPS_PER_CTA + (threadIdx.x >> 5);
    const int lane = threadIdx.x & 31;
    const int m = gw & (M_ - 1);
    const int t = (gw >> 7) & (T_ - 1);
    const int b = gw >> 10;

    int use_t = t;
    if (t != 0 && vl[(b * T_ + t) * M_ + m] == 0) use_t = 0;

    const int slab = b * T_ + use_t;
    const float*  P  = pts + (size_t)slab * N_ * F_;
    const float4* X4 = (const float4*)(g_x + (size_t)slab * N_);
    const float4* Y4 = (const float4*)(g_y + (size_t)slab * N_);
    float* O = out + ((size_t)(b * M_ + m) * (T_ * S_) + (size_t)t * S_) * F_;

    StageBuf A, Bb;
    load_stage(A,  X4, Y4, 0, lane);
    load_stage(Bb, X4, Y4, 1, lane);

    float cx, cy;
    const float thr = roi_setup(rois + ((size_t)slab * M_ + m) * 7, cx, cy);
    const unsigned long long cx2 = pk2(cx, cx);
    const unsigned long long cy2 = pk2(cy, cy);

    int total = 0;
    #pragma unroll 1
    for (int s = 0; s < CAP_STAGES; s += 2) {
        {
            const unsigned mask = stage_mask(A, cx2, cy2, thr);
            if (__ballot_sync(0xFFFFFFFFu, mask != 0))
                total = total + emit_stage(mask, total, s, lane, P, O);
            if (total >= S_) break;
            const int ns = s + 2;
            load_stage(A, X4, Y4, ns < CAP_STAGES ? ns : 0, lane);
        }
        {
            const unsigned mask = stage_mask(Bb, cx2, cy2, thr);
            if (__ballot_sync(0xFFFFFFFFu, mask != 0))
                total = total + emit_stage(mask, total, s + 1, lane, P, O);
            if (total >= S_) break;
            const int ns = s + 3;
            load_stage(Bb, X4, Y4, ns < CAP_STAGES ? ns : 0, lane);
        }
    }

    if (total < S_) {
        // Unfinished: hand off to phase 2 (which also does the zero-fill).
        if (lane == 0) {
            g_total[gw] = total;
            const int qi = atomicAdd(&g_nq, 1);
            g_queue[qi] = gw;
        }
    }
}

// Phase 2: one 512-thread CTA per queued roi, scanning [CAP_PTS, N) with a
// double-buffered chunk pipeline.
__global__ __launch_bounds__(P2T)
void voxel_phase2(const float* __restrict__ pts,
                  const float* __restrict__ rois,
                  const int* __restrict__ vl,
                  float* __restrict__ out)
{
    __shared__ unsigned long long s_cnt[2][P2W];
    const int tid  = threadIdx.x;
    const int lane = tid & 31;
    const int wid  = tid >> 5;
    const int nq = g_nq;

    for (int qi = blockIdx.x; qi < nq; qi += gridDim.x) {
        const int gw = g_queue[qi];
        const int m = gw & (M_ - 1);
        const int t = (gw >> 7) & (T_ - 1);
        const int b = gw >> 10;

        int use_t = t;
        if (t != 0 && vl[(b * T_ + t) * M_ + m] == 0) use_t = 0;

        const int slab = b * T_ + use_t;
        const float*  P  = pts + (size_t)slab * N_ * F_;
        const float4* X4 = (const float4*)(g_x + (size_t)slab * N_);
        const float4* Y4 = (const float4*)(g_y + (size_t)slab * N_);
        float* O = out + ((size_t)(b * M_ + m) * (T_ * S_) + (size_t)t * S_) * F_;

        float cx, cy;
        const float thr = roi_setup(rois + ((size_t)slab * M_ + m) * 7, cx, cy);

        int total = g_total[gw];

        // Double-buffered chunk pipeline.
        float4 xb[2][4], yb[2][4];
        {
            const int b4 = CAP_PTS / 4;
            #pragma unroll
            for (int g = 0; g < 4; g++) {
                xb[0][g] = X4[b4 + g * P2T + tid];
                yb[0][g] = Y4[b4 + g * P2T + tid];
            }
        }

        #pragma unroll 1
        for (int c = 0; c < P2NCH; c++) {
            const int cur = c & 1;
            if (c + 1 < P2NCH) {         // speculative preload of next chunk
                const int b4 = (CAP_PTS + (c + 1) * P2CHUNK) / 4;
                #pragma unroll
                for (int g = 0; g < 4; g++) {
                    xb[cur ^ 1][g] = X4[b4 + g * P2T + tid];
                    yb[cur ^ 1][g] = Y4[b4 + g * P2T + tid];
                }
            }

            const int base = CAP_PTS + c * P2CHUNK;
            unsigned mask = 0;
            #pragma unroll
            for (int g = 0; g < 4; g++) {
                const float* xs = (const float*)&xb[cur][g];
                const float* ys = (const float*)&yb[cur][g];
                #pragma unroll
                for (int k = 0; k < 4; k++) {
                    const float dx = __fsub_rn(xs[k], cx);
                    const float dy = __fsub_rn(ys[k], cy);
                    const float d2 = __fadd_rn(__fmul_rn(dx, dx),
                                               __fmul_rn(dy, dy));
                    mask |= (d2 <= thr ? 1u : 0u) << (g * 4 + k);
                }
            }

            unsigned cp = 0;
            #pragma unroll
            for (int g = 0; g < 4; g++)
                cp |= (unsigned)__popc((mask >> (4 * g)) & 0xFu) << (8 * g);

            unsigned incl = cp;
            #pragma unroll
            for (int d = 1; d < 32; d <<= 1) {
                const unsigned v = __shfl_up_sync(0xFFFFFFFFu, incl, d);
                if (lane >= d) incl += v;
            }
            const unsigned wtot = __shfl_sync(0xFFFFFFFFu, incl, 31);
            const unsigned excl = incl - cp;

            if (lane == 0) s_cnt[cur][wid] = spread4(wtot);
            __syncthreads();

            unsigned long long tot64 = 0, bef64 = 0;
            #pragma unroll
            for (int w = 0; w < P2W; w++) {
                const unsigned long long v = s_cnt[cur][w];
                tot64 += v;
                if (w < wid) bef64 += v;
            }
            const unsigned a = (unsigned)tot64 + (unsigned)(tot64 >> 32);
            const int chunkTotal = (int)((a & 0xFFFFu) + (a >> 16));

            if (mask) {
                int fp = 0;
                #pragma unroll
                for (int g = 0; g < 4; g++) {
                    const int tj = (int)((tot64 >> (16 * g)) & 0xFFFFu);
                    const int bj = (int)((bef64 >> (16 * g)) & 0xFFFFu);
                    int r = total + fp + bj + (int)((excl >> (8 * g)) & 0xFFu);
                    unsigned mj = (mask >> (4 * g)) & 0xFu;
                    while (mj) {
                        const int k = __ffs(mj) - 1;
                        mj &= mj - 1;
                        if (r < S_) {
                            const int pt = base + g * (P2T * 4) + tid * 4 + k;
                            const float* src = P + (size_t)pt * F_;
                            float* dst = O + r * F_;
                            #pragma unroll
                            for (int f = 0; f < F_; f++) dst[f] = src[f];
                        }
                        r++;
                    }
                    fp += tj;
                }
            }

            total += chunkTotal;
            if (total >= S_) break;   // uniform
        }

        // Zero-fill rows [written, S).
        const int written = (total < S_) ? total : S_;
        const int zfl = (S_ - written) * F_;
        for (int i = tid; i < zfl; i += P2T) {
            O[written * F_ + i] = 0.0f;
        }
        __syncthreads();   // protect s_cnt before next queue entry
    }
}

extern "C" void kernel_launch(void* const* d_in, const int* in_sizes, int n_in,
                              void* d_out, int out_size)
{
    const float* pts  = (const float*)d_in[0];  // [B,T,N,F] f32
    const float* rois = (const float*)d_in[1];  // [B,T,M,7] f32
    const int*   vl   = (const int*)d_in[2];    // [B,T,M]   i32
    float* out = (float*)d_out;                 // [B,M,T*S,F] f32

    (void)in_sizes; (void)n_in; (void)out_size;
    transpose_xy_kernel<<<TOTALPTS / 8 / NTHREADS, NTHREADS>>>((const float4*)pts);
    voxel_phase1<<<NWARPSG / WARPS_PER_CTA, NTHREADS>>>(pts, rois, vl, out);
    voxel_phase2<<<P2GRID, P2T>>>(pts, rois, vl, out);
}

// round 9
// speedup vs baseline: 1.3474x; 1.0235x over previous
#include <cuda_runtime.h>
#include <math.h>

// Problem constants: B=2, T=8, N=65536, M=128, F=5, S=128
#define B_ 2
#define T_ 8
#define N_ 65536
#define M_ 128
#define F_ 5
#define S_ 128
#define GAMMA_ 1.1f

#define NTHREADS 256
#define WARPS_PER_CTA 8
#define NWARPSG (B_ * T_ * M_)          // 2048 rois
#define STAGE_PTS 512                   // points per warp-stage (16/lane)
#define CAP_STAGES 16                   // phase-1 cap (divisible by 2)
#define CAP_PTS (CAP_STAGES * STAGE_PTS)        // 8192
#define TOTALPTS (B_ * T_ * N_)         // 1,048,576

// Phase 2: 512-thread CTA, 16 pts/thread -> 8192-pt chunks; (N-CAP)/8192 = 7.
#define P2T 512
#define P2W 16
#define P2CHUNK (P2T * 16)              // 8192
#define P2NCH ((N_ - CAP_PTS) / P2CHUNK)        // 7
#define P2GRID 256

// SoA scratch for xy + phase-1 -> phase-2 handoff state.
__device__ __align__(16) float g_x[TOTALPTS];
__device__ __align__(16) float g_y[TOTALPTS];
__device__ int g_nq;
__device__ int g_queue[NWARPSG];
__device__ int g_total[NWARPSG];

// AoS->SoA transpose: 4 points (= 5 float4) per thread. Also resets the
// phase-2 queue counter (stream-ordered before phase 1).
__global__ __launch_bounds__(NTHREADS)
void transpose_xy_kernel(const float4* __restrict__ pts4)
{
    if (blockIdx.x == 0 && threadIdx.x == 0) g_nq = 0;
    const int i4 = blockIdx.x * NTHREADS + threadIdx.x;
    const float4 p0 = pts4[i4 * 5 + 0];
    const float4 p1 = pts4[i4 * 5 + 1];
    const float4 p2 = pts4[i4 * 5 + 2];
    const float4 p3 = pts4[i4 * 5 + 3];
    const float4 p4 = pts4[i4 * 5 + 4];
    ((float4*)g_x)[i4] = make_float4(p0.x, p1.y, p2.z, p3.w);
    ((float4*)g_y)[i4] = make_float4(p0.y, p1.z, p2.w, p4.x);
}

// ---- packed f32x2 helpers (per-lane exact .rn => bit-identical to scalar) ----
__device__ __forceinline__ unsigned long long pk2(float lo, float hi) {
    unsigned long long r;
    asm("mov.b64 %0, {%1, %2};" : "=l"(r) : "f"(lo), "f"(hi));
    return r;
}
__device__ __forceinline__ unsigned long long sub2(unsigned long long a,
                                                   unsigned long long b) {
    unsigned long long d;
    asm("sub.rn.f32x2 %0, %1, %2;" : "=l"(d) : "l"(a), "l"(b));
    return d;
}
__device__ __forceinline__ unsigned long long mul2(unsigned long long a,
                                                   unsigned long long b) {
    unsigned long long d;
    asm("mul.rn.f32x2 %0, %1, %2;" : "=l"(d) : "l"(a), "l"(b));
    return d;
}
__device__ __forceinline__ unsigned long long add2(unsigned long long a,
                                                   unsigned long long b) {
    unsigned long long d;
    asm("add.rn.f32x2 %0, %1, %2;" : "=l"(d) : "l"(a), "l"(b));
    return d;
}
__device__ __forceinline__ void unpk2(unsigned long long v, float& lo, float& hi) {
    asm("mov.b64 {%0, %1}, %2;" : "=f"(lo), "=f"(hi) : "l"(v));
}

__device__ __forceinline__ unsigned long long spread4(unsigned v)
{
    return (unsigned long long)(v & 0xFFu)
         | ((unsigned long long)(v & 0xFF00u)     << 8)
         | ((unsigned long long)(v & 0xFF0000u)   << 16)
         | ((unsigned long long)(v & 0xFF000000u) << 24);
}

// thr = largest float x with sqrtf(x) <= r  => (d2 <= thr) bit-identical to
// (sqrtf(d2) <= r); removes the per-point sqrt.
__device__ __forceinline__ float roi_setup(const float* __restrict__ roi,
                                           float& cx, float& cy)
{
    cx = roi[0];
    cy = roi[1];
    const float hl = __fmul_rn(roi[3], 0.5f);
    const float hw = __fmul_rn(roi[4], 0.5f);
    const float rr = __fmul_rn(
        sqrtf(__fadd_rn(__fmul_rn(hl, hl), __fmul_rn(hw, hw))), GAMMA_);
    float thr = __fmul_rn(rr, rr);
    while (sqrtf(thr) > rr) thr = __int_as_float(__float_as_int(thr) - 1);
    for (;;) {
        float nxt = __int_as_float(__float_as_int(thr) + 1);
        if (sqrtf(nxt) <= rr) thr = nxt; else break;
    }
    return thr;
}

struct StageBuf { float4 x[4]; float4 y[4]; };

__device__ __forceinline__ void load_stage(StageBuf& sb, const float4* __restrict__ X4,
                                           const float4* __restrict__ Y4,
                                           int s, int lane)
{
    const int b4 = s * (STAGE_PTS / 4);
    #pragma unroll
    for (int g = 0; g < 4; g++) {
        sb.x[g] = X4[b4 + g * 32 + lane];
        sb.y[g] = Y4[b4 + g * 32 + lane];
    }
}

__device__ __forceinline__ unsigned stage_mask(const StageBuf& sb,
                                               unsigned long long cx2,
                                               unsigned long long cy2, float thr)
{
    unsigned mask = 0;
    #pragma unroll
    for (int g = 0; g < 4; g++) {
        const unsigned long long x01 = pk2(sb.x[g].x, sb.x[g].y);
        const unsigned long long x23 = pk2(sb.x[g].z, sb.x[g].w);
        const unsigned long long y01 = pk2(sb.y[g].x, sb.y[g].y);
        const unsigned long long y23 = pk2(sb.y[g].z, sb.y[g].w);
        const unsigned long long dx01 = sub2(x01, cx2);
        const unsigned long long dx23 = sub2(x23, cx2);
        const unsigned long long dy01 = sub2(y01, cy2);
        const unsigned long long dy23 = sub2(y23, cy2);
        const unsigned long long d01 = add2(mul2(dx01, dx01), mul2(dy01, dy01));
        const unsigned long long d23 = add2(mul2(dx23, dx23), mul2(dy23, dy23));
        float d0, d1, d2, d3;
        unpk2(d01, d0, d1);
        unpk2(d23, d2, d3);
        mask |= (d0 <= thr ? 1u : 0u) << (g * 4 + 0);
        mask |= (d1 <= thr ? 1u : 0u) << (g * 4 + 1);
        mask |= (d2 <= thr ? 1u : 0u) << (g * 4 + 2);
        mask |= (d3 <= thr ? 1u : 0u) << (g * 4 + 3);
    }
    return mask;
}

// Warp-only ordered write of a matching stage. Returns stage total (uniform).
__device__ __forceinline__ int emit_stage(unsigned mask, int total, int s, int lane,
                                          const float* __restrict__ P,
                                          float* __restrict__ O)
{
    unsigned cp = 0;
    #pragma unroll
    for (int g = 0; g < 4; g++)
        cp |= (unsigned)__popc((mask >> (4 * g)) & 0xFu) << (8 * g);

    unsigned incl = cp;
    #pragma unroll
    for (int d = 1; d < 32; d <<= 1) {
        const unsigned v = __shfl_up_sync(0xFFFFFFFFu, incl, d);
        if (lane >= d) incl += v;
    }
    const unsigned wtot = __shfl_sync(0xFFFFFFFFu, incl, 31);
    const unsigned excl = incl - cp;

    if (mask) {
        int fp = 0;
        #pragma unroll
        for (int g = 0; g < 4; g++) {
            int r = total + fp + (int)((excl >> (8 * g)) & 0xFFu);
            unsigned mj = (mask >> (4 * g)) & 0xFu;
            while (mj) {
                const int k = __ffs(mj) - 1;
                mj &= mj - 1;
                if (r < S_) {
                    const int pt = s * STAGE_PTS + g * 128 + lane * 4 + k;
                    const float* src = P + (size_t)pt * F_;
                    float* dst = O + r * F_;
                    #pragma unroll
                    for (int f = 0; f < F_; f++) dst[f] = src[f];
                }
                r++;
            }
            fp += (int)((wtot >> (8 * g)) & 0xFFu);
        }
    }
    const unsigned a = (wtot & 0x00FF00FFu) + ((wtot >> 8) & 0x00FF00FFu);
    return (int)((a & 0xFFFFu) + (a >> 16));
}

// Phase 1: one WARP per roi, capped at CAP_STAGES (8192 pts). Depth-2
// pipeline. NOTE: no min-blocks occupancy forcing -- letting ptxas use its
// natural register budget avoids local-memory spills.
__global__ __launch_bounds__(NTHREADS)
void voxel_phase1(const float* __restrict__ pts,
                  const float* __restrict__ rois,
                  const int* __restrict__ vl,
                  float* __restrict__ out)
{
    const int gw = blockIdx.x * WARPS_PER_CTA + (threadIdx.x >> 5);
    const int lane = threadIdx.x & 31;
    const int m = gw & (M_ - 1);
    const int t = (gw >> 7) & (T_ - 1);
    const int b = gw >> 10;

    int use_t = t;
    if (t != 0 && vl[(b * T_ + t) * M_ + m] == 0) use_t = 0;

    const int slab = b * T_ + use_t;
    const float*  P  = pts + (size_t)slab * N_ * F_;
    const float4* X4 = (const float4*)(g_x + (size_t)slab * N_);
    const float4* Y4 = (const float4*)(g_y + (size_t)slab * N_);
    float* O = out + ((size_t)(b * M_ + m) * (T_ * S_) + (size_t)t * S_) * F_;

    StageBuf A, Bb;
    load_stage(A,  X4, Y4, 0, lane);
    load_stage(Bb, X4, Y4, 1, lane);

    float cx, cy;
    const float thr = roi_setup(rois + ((size_t)slab * M_ + m) * 7, cx, cy);
    const unsigned long long cx2 = pk2(cx, cx);
    const unsigned long long cy2 = pk2(cy, cy);

    int total = 0;
    #pragma unroll 1
    for (int s = 0; s < CAP_STAGES; s += 2) {
        {
            const unsigned mask = stage_mask(A, cx2, cy2, thr);
            if (__ballot_sync(0xFFFFFFFFu, mask != 0))
                total = total + emit_stage(mask, total, s, lane, P, O);
            if (total >= S_) break;
            const int ns = s + 2;
            load_stage(A, X4, Y4, ns < CAP_STAGES ? ns : 0, lane);
        }
        {
            const unsigned mask = stage_mask(Bb, cx2, cy2, thr);
            if (__ballot_sync(0xFFFFFFFFu, mask != 0))
                total = total + emit_stage(mask, total, s + 1, lane, P, O);
            if (total >= S_) break;
            const int ns = s + 3;
            load_stage(Bb, X4, Y4, ns < CAP_STAGES ? ns : 0, lane);
        }
    }

    if (total < S_) {
        // Unfinished: hand off to phase 2 (which also does the zero-fill).
        if (lane == 0) {
            g_total[gw] = total;
            const int qi = atomicAdd(&g_nq, 1);
            g_queue[qi] = gw;
        }
    }
}

// Phase 2: one 512-thread CTA per queued roi, scanning [CAP_PTS, N) with a
// double-buffered chunk pipeline.
__global__ __launch_bounds__(P2T)
void voxel_phase2(const float* __restrict__ pts,
                  const float* __restrict__ rois,
                  const int* __restrict__ vl,
                  float* __restrict__ out)
{
    __shared__ unsigned long long s_cnt[2][P2W];
    const int tid  = threadIdx.x;
    const int lane = tid & 31;
    const int wid  = tid >> 5;
    const int nq = g_nq;

    for (int qi = blockIdx.x; qi < nq; qi += gridDim.x) {
        const int gw = g_queue[qi];
        const int m = gw & (M_ - 1);
        const int t = (gw >> 7) & (T_ - 1);
        const int b = gw >> 10;

        int use_t = t;
        if (t != 0 && vl[(b * T_ + t) * M_ + m] == 0) use_t = 0;

        const int slab = b * T_ + use_t;
        const float*  P  = pts + (size_t)slab * N_ * F_;
        const float4* X4 = (const float4*)(g_x + (size_t)slab * N_);
        const float4* Y4 = (const float4*)(g_y + (size_t)slab * N_);
        float* O = out + ((size_t)(b * M_ + m) * (T_ * S_) + (size_t)t * S_) * F_;

        float cx, cy;
        const float thr = roi_setup(rois + ((size_t)slab * M_ + m) * 7, cx, cy);

        int total = g_total[gw];

        // Double-buffered chunk pipeline.
        float4 xb[2][4], yb[2][4];
        {
            const int b4 = CAP_PTS / 4;
            #pragma unroll
            for (int g = 0; g < 4; g++) {
                xb[0][g] = X4[b4 + g * P2T + tid];
                yb[0][g] = Y4[b4 + g * P2T + tid];
            }
        }

        #pragma unroll 1
        for (int c = 0; c < P2NCH; c++) {
            const int cur = c & 1;
            if (c + 1 < P2NCH) {         // speculative preload of next chunk
                const int b4 = (CAP_PTS + (c + 1) * P2CHUNK) / 4;
                #pragma unroll
                for (int g = 0; g < 4; g++) {
                    xb[cur ^ 1][g] = X4[b4 + g * P2T + tid];
                    yb[cur ^ 1][g] = Y4[b4 + g * P2T + tid];
                }
            }

            const int base = CAP_PTS + c * P2CHUNK;
            unsigned mask = 0;
            #pragma unroll
            for (int g = 0; g < 4; g++) {
                const float* xs = (const float*)&xb[cur][g];
                const float* ys = (const float*)&yb[cur][g];
                #pragma unroll
                for (int k = 0; k < 4; k++) {
                    const float dx = __fsub_rn(xs[k], cx);
                    const float dy = __fsub_rn(ys[k], cy);
                    const float d2 = __fadd_rn(__fmul_rn(dx, dx),
                                               __fmul_rn(dy, dy));
                    mask |= (d2 <= thr ? 1u : 0u) << (g * 4 + k);
                }
            }

            unsigned cp = 0;
            #pragma unroll
            for (int g = 0; g < 4; g++)
                cp |= (unsigned)__popc((mask >> (4 * g)) & 0xFu) << (8 * g);

            unsigned incl = cp;
            #pragma unroll
            for (int d = 1; d < 32; d <<= 1) {
                const unsigned v = __shfl_up_sync(0xFFFFFFFFu, incl, d);
                if (lane >= d) incl += v;
            }
            const unsigned wtot = __shfl_sync(0xFFFFFFFFu, incl, 31);
            const unsigned excl = incl - cp;

            if (lane == 0) s_cnt[cur][wid] = spread4(wtot);
            __syncthreads();

            unsigned long long tot64 = 0, bef64 = 0;
            #pragma unroll
            for (int w = 0; w < P2W; w++) {
                const unsigned long long v = s_cnt[cur][w];
                tot64 += v;
                if (w < wid) bef64 += v;
            }
            const unsigned a = (unsigned)tot64 + (unsigned)(tot64 >> 32);
            const int chunkTotal = (int)((a & 0xFFFFu) + (a >> 16));

            if (mask) {
                int fp = 0;
                #pragma unroll
                for (int g = 0; g < 4; g++) {
                    const int tj = (int)((tot64 >> (16 * g)) & 0xFFFFu);
                    const int bj = (int)((bef64 >> (16 * g)) & 0xFFFFu);
                    int r = total + fp + bj + (int)((excl >> (8 * g)) & 0xFFu);
                    unsigned mj = (mask >> (4 * g)) & 0xFu;
                    while (mj) {
                        const int k = __ffs(mj) - 1;
                        mj &= mj - 1;
                        if (r < S_) {
                            const int pt = base + g * (P2T * 4) + tid * 4 + k;
                            const float* src = P + (size_t)pt * F_;
                            float* dst = O + r * F_;
                            #pragma unroll
                            for (int f = 0; f < F_; f++) dst[f] = src[f];
                        }
                        r++;
                    }
                    fp += tj;
                }
            }

            total += chunkTotal;
            if (total >= S_) break;   // uniform
        }

        // Zero-fill rows [written, S).
        const int written = (total < S_) ? total : S_;
        const int zfl = (S_ - written) * F_;
        for (int i = tid; i < zfl; i += P2T) {
            O[written * F_ + i] = 0.0f;
        }
        __syncthreads();   // protect s_cnt before next queue entry
    }
}

extern "C" void kernel_launch(void* const* d_in, const int* in_sizes, int n_in,
                              void* d_out, int out_size)
{
    const float* pts  = (const float*)d_in[0];  // [B,T,N,F] f32
    const float* rois = (const float*)d_in[1];  // [B,T,M,7] f32
    const int*   vl   = (const int*)d_in[2];    // [B,T,M]   i32
    float* out = (float*)d_out;                 // [B,M,T*S,F] f32

    (void)in_sizes; (void)n_in; (void)out_size;
    transpose_xy_kernel<<<TOTALPTS / 4 / NTHREADS, NTHREADS>>>((const float4*)pts);
    voxel_phase1<<<NWARPSG / WARPS_PER_CTA, NTHREADS>>>(pts, rois, vl, out);
    voxel_phase2<<<P2GRID, P2T>>>(pts, rois, vl, out);
}